// round 15
// baseline (speedup 1.0000x reference)
#include <cuda_runtime.h>
#include <cuda_fp16.h>
#include <cstdint>

#define N_NODES 50000
#define N_EDGES 800000
#define E_UND   400000
#define D 64
#define NG 128
#define SCAN_NB 49   // ceil(50000 / 1024)

// ---------------- scratch (device globals: no runtime allocation) ----------
// Messages live in CSR(dst) POSITION space: position p holds edge eidx[p].
__device__ __align__(16) __half g_node_lin[(size_t)N_NODES * D];
__device__ __align__(16) __half g_imt[(size_t)N_EDGES * D];   // imt[p] = im[rev(eidx[p])]
__device__ __align__(16) __half g_curA[(size_t)N_EDGES * D];  // ping
__device__ __align__(16) __half g_curB[(size_t)N_EDGES * D];  // pong
__device__ __align__(16) __half g_agg[(size_t)N_NODES * D];
__device__ __align__(16) __half g_Wc16[64 * 64];
__device__ __align__(16) __half g_We16[32 * 64];
__device__ int g_cnt[N_NODES];       // BSS-zero; k_scanC re-zeroes each call
__device__ int g_off[N_NODES + 1];
__device__ int g_cursor[N_NODES];
__device__ int g_part[SCAN_NB];
__device__ int g_eidx[N_EDGES];      // position -> edge
__device__ int g_pnode[N_EDGES];     // position -> node (dst of that edge)
__device__ int g_perm[N_EDGES];      // edge -> position
__device__ int g_wq[N_EDGES];        // edge e -> perm[rev(e)]
__device__ int g_tw[N_EDGES];        // position p -> perm[rev(eidx[p])]

// ---------------- mma helpers ----------------------------------------------
__device__ __forceinline__ void ldmA(uint32_t a[4], uint32_t addr) {
    asm volatile("ldmatrix.sync.aligned.m8n8.x4.shared.b16 {%0,%1,%2,%3}, [%4];"
                 : "=r"(a[0]), "=r"(a[1]), "=r"(a[2]), "=r"(a[3]) : "r"(addr));
}
__device__ __forceinline__ void ldmBt4(uint32_t b[4], uint32_t addr) {
    asm volatile("ldmatrix.sync.aligned.m8n8.x4.trans.shared.b16 {%0,%1,%2,%3}, [%4];"
                 : "=r"(b[0]), "=r"(b[1]), "=r"(b[2]), "=r"(b[3]) : "r"(addr));
}
__device__ __forceinline__ void mma16816(float d[4], const uint32_t a[4],
                                         const uint32_t b[2]) {
    asm volatile(
        "mma.sync.aligned.m16n8k16.row.col.f32.f16.f16.f32 "
        "{%0,%1,%2,%3}, {%4,%5,%6,%7}, {%8,%9}, {%0,%1,%2,%3};"
        : "+f"(d[0]), "+f"(d[1]), "+f"(d[2]), "+f"(d[3])
        : "r"(a[0]), "r"(a[1]), "r"(a[2]), "r"(a[3]), "r"(b[0]), "r"(b[1]));
}

#define NL_THREADS 200192  // 782 blocks * 256

// ---------------- 3-phase parallel scan -------------------------------------
// A: per-block reduce of cnt -> g_part[b]
__global__ void __launch_bounds__(1024) k_scanA() {
    __shared__ int wsum[32];
    int t = threadIdx.x;
    int lane = t & 31, w = t >> 5;
    int idx = blockIdx.x * 1024 + t;
    int x = (idx < N_NODES) ? g_cnt[idx] : 0;
#pragma unroll
    for (int o = 16; o >= 1; o >>= 1) x += __shfl_down_sync(0xffffffffu, x, o);
    if (lane == 0) wsum[w] = x;
    __syncthreads();
    if (w == 0) {
        int y = wsum[lane];
#pragma unroll
        for (int o = 16; o >= 1; o >>= 1) y += __shfl_down_sync(0xffffffffu, y, o);
        if (lane == 0) g_part[blockIdx.x] = y;
    }
}

// B: serial exclusive scan of 49 partials (thread 0) + zero out
__global__ void k_scanB(float* __restrict__ out) {
    int t = threadIdx.x;
    for (int i = t; i < NG * D; i += 256) out[i] = 0.0f;
    if (t == 0) {
        int run = 0;
#pragma unroll 1
        for (int i = 0; i < SCAN_NB; ++i) {
            int v = g_part[i];
            g_part[i] = run;
            run += v;
        }
    }
}

// C: block-local exclusive scan + base; writes off/cursor, zeroes cnt
__global__ void __launch_bounds__(1024) k_scanC() {
    __shared__ int wsum[32];
    int t = threadIdx.x;
    int lane = t & 31, w = t >> 5;
    int idx = blockIdx.x * 1024 + t;
    int v = (idx < N_NODES) ? g_cnt[idx] : 0;
    int x = v;
#pragma unroll
    for (int o = 1; o < 32; o <<= 1) {
        int y = __shfl_up_sync(0xffffffffu, x, o);
        if (lane >= o) x += y;
    }
    if (lane == 31) wsum[w] = x;
    __syncthreads();
    if (w == 0) {
        int y = wsum[lane];
#pragma unroll
        for (int o = 1; o < 32; o <<= 1) {
            int z = __shfl_up_sync(0xffffffffu, y, o);
            if (lane >= o) y += z;
        }
        wsum[lane] = y;
    }
    __syncthreads();
    int excl = g_part[blockIdx.x] + x - v + (w > 0 ? wsum[w - 1] : 0);
    if (idx < N_NODES) {
        g_off[idx] = excl;
        g_cursor[idx] = excl;
        g_cnt[idx] = 0;
        if (idx == N_NODES - 1) g_off[N_NODES] = excl + v;
    }
}

// ---------------- scatter: build position-space index arrays ----------------
__global__ void k_scatter(const int* __restrict__ dst) {
    int e = blockIdx.x * blockDim.x + threadIdx.x;
    if (e < N_EDGES) {
        int d = dst[e];
        int p = atomicAdd(&g_cursor[d], 1);
        g_eidx[p] = e;
        g_pnode[p] = d;
        g_perm[e] = p;
        int r = (e < E_UND) ? e + E_UND : e - E_UND;  // rev(e)
        g_wq[r] = p;                                  // wq[rev(e)] = perm[e]
    }
}

// ---------------- segment sum: warp per node, CONTIGUOUS rows ---------------
__device__ __forceinline__ void seg_accum(uint4 v, float2& a0, float2& a1,
                                          float2& a2, float2& a3) {
    const __half2* h = (const __half2*)&v;
    float2 f0 = __half22float2(h[0]);
    float2 f1 = __half22float2(h[1]);
    float2 f2 = __half22float2(h[2]);
    float2 f3 = __half22float2(h[3]);
    a0.x += f0.x; a0.y += f0.y;
    a1.x += f1.x; a1.y += f1.y;
    a2.x += f2.x; a2.y += f2.y;
    a3.x += f3.x; a3.y += f3.y;
}

template <bool SRCB>
__global__ void __launch_bounds__(256) k_segsum() {
    int gw = (blockIdx.x * 256 + threadIdx.x) >> 5;
    int lane = threadIdx.x & 31;
    if (gw >= N_NODES) return;
    const __half* __restrict__ srcp = SRCB ? g_curB : g_curA;
    int beg = g_off[gw], end = g_off[gw + 1];
    int g = lane >> 3, s = lane & 7;
    float2 a0 = {0.f, 0.f}, a1 = {0.f, 0.f}, a2 = {0.f, 0.f}, a3 = {0.f, 0.f};
    int j = beg;
    for (; j + 16 <= end; j += 16) {
        uint4 v[4];
#pragma unroll
        for (int q = 0; q < 4; ++q)
            v[q] = *(const uint4*)(srcp + (size_t)(j + q * 4 + g) * D + s * 8);
#pragma unroll
        for (int q = 0; q < 4; ++q) seg_accum(v[q], a0, a1, a2, a3);
    }
    for (; j + 8 <= end; j += 8) {
        uint4 v[2];
#pragma unroll
        for (int q = 0; q < 2; ++q)
            v[q] = *(const uint4*)(srcp + (size_t)(j + q * 4 + g) * D + s * 8);
#pragma unroll
        for (int q = 0; q < 2; ++q) seg_accum(v[q], a0, a1, a2, a3);
    }
    for (; j < end; j += 4) {
        int r = j + g;
        uint4 v = make_uint4(0u, 0u, 0u, 0u);
        if (r < end) v = *(const uint4*)(srcp + (size_t)r * D + s * 8);
        seg_accum(v, a0, a1, a2, a3);
    }
#pragma unroll
    for (int off = 16; off >= 8; off >>= 1) {
        a0.x += __shfl_down_sync(0xffffffffu, a0.x, off);
        a0.y += __shfl_down_sync(0xffffffffu, a0.y, off);
        a1.x += __shfl_down_sync(0xffffffffu, a1.x, off);
        a1.y += __shfl_down_sync(0xffffffffu, a1.y, off);
        a2.x += __shfl_down_sync(0xffffffffu, a2.x, off);
        a2.y += __shfl_down_sync(0xffffffffu, a2.y, off);
        a3.x += __shfl_down_sync(0xffffffffu, a3.x, off);
        a3.y += __shfl_down_sync(0xffffffffu, a3.y, off);
    }
    if (lane < 8) {
        __half2 h[4];
        h[0] = __floats2half2_rn(a0.x, a0.y);
        h[1] = __floats2half2_rn(a1.x, a1.y);
        h[2] = __floats2half2_rn(a2.x, a2.y);
        h[3] = __floats2half2_rn(a3.x, a3.y);
        *(uint4*)(g_agg + (size_t)gw * D + lane * 8) = *(const uint4*)h;
    }
}

// ---------------- fp32 4x4-microtile GEMM core (small GEMMs) ---------------
template <int K, int XS>
__device__ __forceinline__ void gemm_tile(const float* __restrict__ Xs,
                                          const float* __restrict__ Ws,
                                          int r0, int c0, float acc[4][4]) {
#pragma unroll
    for (int k4 = 0; k4 < K / 4; ++k4) {
        float w[4][4];
#pragma unroll
        for (int kk = 0; kk < 4; ++kk) {
            float4 wv = *(const float4*)&Ws[(k4 * 4 + kk) * 64 + c0];
            w[kk][0] = wv.x; w[kk][1] = wv.y; w[kk][2] = wv.z; w[kk][3] = wv.w;
        }
#pragma unroll
        for (int i = 0; i < 4; ++i) {
            float4 xv = *(const float4*)&Xs[(r0 + i) * XS + k4 * 4];
#pragma unroll
            for (int jj = 0; jj < 4; ++jj) {
                acc[i][jj] = fmaf(xv.x, w[0][jj], acc[i][jj]);
                acc[i][jj] = fmaf(xv.y, w[1][jj], acc[i][jj]);
                acc[i][jj] = fmaf(xv.z, w[2][jj], acc[i][jj]);
                acc[i][jj] = fmaf(xv.w, w[3][jj], acc[i][jj]);
            }
        }
    }
}

// ---------------- A: node_lin GEMM + dst histogram + weight converts --------
__global__ void __launch_bounds__(256) k_nodelin(const float* __restrict__ nf,
                                                 const float* __restrict__ Wn,
                                                 const float* __restrict__ bn,
                                                 const int* __restrict__ dst,
                                                 const float* __restrict__ Wc,
                                                 const float* __restrict__ We) {
    __shared__ __align__(16) float Xs[64 * 68];
    __shared__ __align__(16) float Ws[64 * 64];
    int t = threadIdx.x;
    int n0 = blockIdx.x * 64;
    int valid = N_NODES - n0; if (valid > 64) valid = 64;

    {   // piggyback: dst histogram
        int gid = blockIdx.x * 256 + t;
#pragma unroll
        for (int q = 0; q < 4; ++q) {
            int e = gid + q * NL_THREADS;
            if (e < N_EDGES) atomicAdd(&g_cnt[dst[e]], 1);
        }
    }
    if (blockIdx.x == 0) {  // piggyback: fp16 weight conversion
        for (int i = t; i < 64 * 64; i += 256) g_Wc16[i] = __float2half(Wc[i]);
        for (int i = t; i < 32 * 64; i += 256) g_We16[i] = __float2half(We[i]);
    }

    float4* Wsv = (float4*)Ws;
    const float4* Wg = (const float4*)Wn;
#pragma unroll
    for (int j = 0; j < 4; ++j) Wsv[t + 256 * j] = Wg[t + 256 * j];
#pragma unroll
    for (int j = 0; j < 4; ++j) {
        int f = j * 256 + t;
        int r = f >> 4, c4 = f & 15;
        float4 x = make_float4(0.f, 0.f, 0.f, 0.f);
        if (r < valid) x = *(const float4*)&nf[(size_t)(n0 + r) * 64 + c4 * 4];
        *(float4*)&Xs[r * 68 + c4 * 4] = x;
    }
    __syncthreads();

    int tx = t & 15, ty = t >> 4, r0 = ty * 4, c0 = tx * 4;
    float acc[4][4];
#pragma unroll
    for (int i = 0; i < 4; ++i)
#pragma unroll
        for (int j = 0; j < 4; ++j) acc[i][j] = 0.f;
    gemm_tile<64, 68>(Xs, Ws, r0, c0, acc);

    float4 bv = *(const float4*)&bn[c0];
#pragma unroll
    for (int i = 0; i < 4; ++i) {
        int r = r0 + i;
        if (r < valid) {
            __half2 h[2];
            h[0] = __floats2half2_rn(acc[i][0] + bv.x, acc[i][1] + bv.y);
            h[1] = __floats2half2_rn(acc[i][2] + bv.z, acc[i][3] + bv.w);
            *(uint2*)&g_node_lin[(size_t)(n0 + r) * 64 + c0] = *(const uint2*)h;
        }
    }
}

// ---------------- B: im init via HMMA, 64 edges/block, 16x32 per warp -------
// Staged half2 epilogue (bias pre-added); writes imt[wq[f]] and curA[perm[f]].
// Preamble also materializes tw[p] = wq[eidx[p]] (consumed by k_update).
__global__ void __launch_bounds__(256) k_im(const float* __restrict__ ef,
                                            const int* __restrict__ src,
                                            const float* __restrict__ be) {
    __shared__ __align__(16) char s_buf[9728];   // Xs(5120)+Ws(4608); accH(9216)
    __shared__ int s_src[64];
    __shared__ int s_q1[64];    // perm[f]  (curA target)
    __shared__ int s_q2[64];    // wq[f]    (imt target)
    __shared__ float s_be[64];
    __half* Xs = (__half*)s_buf;                // 64*40 halves
    __half* Ws = (__half*)(s_buf + 64 * 40 * 2);// 32*72 halves
    __half* accH = (__half*)s_buf;              // 64*72 halves (phase B)
    int t = threadIdx.x;
    int e0 = blockIdx.x * 64;

    {   // piggyback: tw materialization (grid covers 3.2M threads >= N_EDGES)
        int gid = blockIdx.x * 256 + t;
        if (gid < N_EDGES) g_tw[gid] = g_wq[g_eidx[gid]];
    }
    if (t < 64) {
        s_src[t] = src[e0 + t];
        s_q1[t] = g_perm[e0 + t];
        s_q2[t] = g_wq[e0 + t];
        s_be[t] = be[t];
    }
    {   // Ws: 32x64 halves = 256 uint4, stride 72 (1 per thread)
        int row = t >> 3, col = (t & 7) * 8;
        *(uint4*)&Ws[row * 72 + col] = ((const uint4*)g_We16)[t];
    }
    {   // Xs: edge_feat fp32 -> fp16; thread = quarter row (8 cols)
        int r = t >> 2, cs = (t & 3) * 8;
        const float4* xg = (const float4*)(ef + (size_t)(e0 + r) * 32 + cs);
        float4 a = __ldcs(xg);
        float4 b = __ldcs(xg + 1);
        __half2 xh[4];
        xh[0] = __floats2half2_rn(a.x, a.y);
        xh[1] = __floats2half2_rn(a.z, a.w);
        xh[2] = __floats2half2_rn(b.x, b.y);
        xh[3] = __floats2half2_rn(b.z, b.w);
        *(uint4*)&Xs[r * 40 + cs] = *(const uint4*)xh;
    }
    __syncthreads();

    int w = t >> 5, l = t & 31;
    int rg = w >> 1, ch = w & 1;   // row group 0..3, column half 0..1
    int r0w = rg * 16;
    uint32_t baseX = (uint32_t)__cvta_generic_to_shared(Xs);
    uint32_t baseW = (uint32_t)__cvta_generic_to_shared(Ws);
    float acc[4][4];
#pragma unroll
    for (int nt = 0; nt < 4; ++nt)
#pragma unroll
        for (int q = 0; q < 4; ++q) acc[nt][q] = 0.f;

#pragma unroll
    for (int kt = 0; kt < 2; ++kt) {
        uint32_t a[4];
        uint32_t addrA = baseX + (((r0w + (l & 15)) * 40 + kt * 16 + ((l >> 4) << 3)) << 1);
        ldmA(a, addrA);
#pragma unroll
        for (int ntp = 0; ntp < 2; ++ntp) {
            uint32_t b[4];
            uint32_t addrB = baseW +
                (((kt * 16 + (l & 15)) * 72 + ch * 32 + ntp * 16 + ((l >> 4) << 3)) << 1);
            ldmBt4(b, addrB);
            mma16816(acc[2 * ntp], a, b);
            mma16816(acc[2 * ntp + 1], a, b + 2);
        }
    }
    __syncthreads();  // all MMA reads of Xs/Ws done; reuse as accH

    {   // stage (acc + bias) as half2
        int g = l >> 2, tt = l & 3;
        int row1 = r0w + g, row2 = row1 + 8;
#pragma unroll
        for (int nt = 0; nt < 4; ++nt) {
            int c = ch * 32 + nt * 8 + tt * 2;
            float bx = s_be[c], by = s_be[c + 1];
            *(__half2*)&accH[row1 * 72 + c] = __floats2half2_rn(acc[nt][0] + bx, acc[nt][1] + by);
            *(__half2*)&accH[row2 * 72 + c] = __floats2half2_rn(acc[nt][2] + bx, acc[nt][3] + by);
        }
    }
    __syncthreads();

    // writer: rows 0..63, lane owns 8 consecutive cols; scatter stores
#pragma unroll
    for (int p = 0; p < 2; ++p) {
        int row = p * 32 + (t >> 3);
        int c0 = (t & 7) * 8;
        int n = s_src[row];
        uint4 sv = *(const uint4*)&accH[row * 72 + c0];
        const __half2* sh = (const __half2*)&sv;
        uint4 nv = *(const uint4*)(g_node_lin + (size_t)n * 64 + c0);  // 8 halves
        const __half2* nh = (const __half2*)&nv;
        __half2 h[4], hr[4];
#pragma unroll
        for (int q = 0; q < 4; ++q) {
            float2 s = __half22float2(sh[q]);
            float2 nl = __half22float2(nh[q]);
            float yx = s.x + nl.x;
            float yy = s.y + nl.y;
            h[q]  = __floats2half2_rn(yx, yy);
            hr[q] = __floats2half2_rn(fmaxf(yx, 0.f), fmaxf(yy, 0.f));
        }
        *(uint4*)(g_imt + (size_t)s_q2[row] * 64 + c0) = *(const uint4*)h;
        *(uint4*)(g_curA + (size_t)s_q1[row] * 64 + c0) = *(const uint4*)hr;
    }
}

// ---------------- C: BP update, 64 positions/block, 16x32 per warp ----------
// X_p = agg[pnode[p]] - cur[p]; out = relu(X @ Wc + bc + imt[p]) -> cur'[tw[p]].
// Staged half2 epilogue with bias pre-added.
template <bool SRCB>
__global__ void __launch_bounds__(256) k_update(const float* __restrict__ bc) {
    __shared__ __align__(16) char s_buf[64 * 72 * 2 * 2];  // 18432 B
    __shared__ int s_node[64];
    __shared__ int s_tw[64];
    __shared__ float s_bc[64];
    __half* Xs = (__half*)s_buf;                 // 64*72 halves
    __half* Ws = (__half*)(s_buf + 64 * 72 * 2); // 64*72 halves
    __half* accH = (__half*)s_buf;               // 64*72 halves (phase B)
    int t = threadIdx.x;
    int p0 = blockIdx.x * 64;
    const __half* __restrict__ curs = SRCB ? g_curB : g_curA;
    __half* __restrict__ curd = SRCB ? g_curA : g_curB;

    if (t < 64) {
        s_node[t] = g_pnode[p0 + t];
        s_tw[t] = g_tw[p0 + t];
        s_bc[t] = bc[t];
    }
    // Ws: 64x64 halves = 512 uint4, stride 72
#pragma unroll
    for (int j = 0; j < 2; ++j) {
        int idx = j * 256 + t;
        int row = idx >> 3, col = (idx & 7) * 8;
        *(uint4*)&Ws[row * 72 + col] = ((const uint4*)g_Wc16)[idx];
    }
    __syncthreads();

    {   // Xs build: X = agg[node] - cur[p]; thread = quarter row (16 halves)
        int r = t >> 2, cs = (t & 3) * 16;
        int node = s_node[r];
        const uint4* ag4 = (const uint4*)(g_agg + (size_t)node * 64 + cs);
        const uint4* cu4 = (const uint4*)(curs + (size_t)(p0 + r) * 64 + cs);
        uint4 av[2] = {ag4[0], ag4[1]};
        uint4 cv[2] = {__ldcs(cu4), __ldcs(cu4 + 1)};  // old cur dead after
        const __half2* ah = (const __half2*)av;
        const __half2* ch = (const __half2*)cv;
        __half2 xh[8];
#pragma unroll
        for (int q = 0; q < 8; ++q) {
            float2 a = __half22float2(ah[q]);
            float2 c = __half22float2(ch[q]);
            xh[q] = __floats2half2_rn(a.x - c.x, a.y - c.y);
        }
        uint4* dp = (uint4*)&Xs[r * 72 + cs];
        const uint4* sp = (const uint4*)xh;
        dp[0] = sp[0]; dp[1] = sp[1];
    }
    __syncthreads();

    int w = t >> 5, l = t & 31;
    int rg = w >> 1, ch2 = w & 1;
    int r0w = rg * 16;
    uint32_t baseX = (uint32_t)__cvta_generic_to_shared(Xs);
    uint32_t baseW = (uint32_t)__cvta_generic_to_shared(Ws);
    float acc[4][4];
#pragma unroll
    for (int nt = 0; nt < 4; ++nt)
#pragma unroll
        for (int q = 0; q < 4; ++q) acc[nt][q] = 0.f;

#pragma unroll
    for (int kt = 0; kt < 4; ++kt) {
        uint32_t a[4];
        uint32_t addrA = baseX + (((r0w + (l & 15)) * 72 + kt * 16 + ((l >> 4) << 3)) << 1);
        ldmA(a, addrA);
#pragma unroll
        for (int ntp = 0; ntp < 2; ++ntp) {
            uint32_t b[4];
            uint32_t addrB = baseW +
                (((kt * 16 + (l & 15)) * 72 + ch2 * 32 + ntp * 16 + ((l >> 4) << 3)) << 1);
            ldmBt4(b, addrB);
            mma16816(acc[2 * ntp], a, b);
            mma16816(acc[2 * ntp + 1], a, b + 2);
        }
    }
    __syncthreads();  // all MMA reads of Xs/Ws done; reuse as accH

    {   // stage (acc + bias) as half2
        int g = l >> 2, tt = l & 3;
        int row1 = r0w + g, row2 = row1 + 8;
#pragma unroll
        for (int nt = 0; nt < 4; ++nt) {
            int c = ch2 * 32 + nt * 8 + tt * 2;
            float bx = s_bc[c], by = s_bc[c + 1];
            *(__half2*)&accH[row1 * 72 + c] = __floats2half2_rn(acc[nt][0] + bx, acc[nt][1] + by);
            *(__half2*)&accH[row2 * 72 + c] = __floats2half2_rn(acc[nt][2] + bx, acc[nt][3] + by);
        }
    }
    __syncthreads();

    // writer: contiguous imt read, scatter store to curd[tw[p]]
#pragma unroll
    for (int p = 0; p < 2; ++p) {
        int row = p * 32 + (t >> 3);
        int c0 = (t & 7) * 8;
        uint4 sv = *(const uint4*)&accH[row * 72 + c0];
        const __half2* sh = (const __half2*)&sv;
        uint4 imv = __ldcs((const uint4*)(g_imt + (size_t)(p0 + row) * 64 + c0));
        const __half2* mh = (const __half2*)&imv;
        __half2 h[4];
#pragma unroll
        for (int q = 0; q < 4; ++q) {
            float2 s = __half22float2(sh[q]);
            float2 m = __half22float2(mh[q]);
            h[q] = __floats2half2_rn(fmaxf(s.x + m.x, 0.f), fmaxf(s.y + m.y, 0.f));
        }
        *(uint4*)(curd + (size_t)s_tw[row] * 64 + c0) = *(const uint4*)h;
    }
}

// ---------------- D: node readout + per-graph reduction ---------------------
__global__ void __launch_bounds__(256) k_out(const int* __restrict__ gids,
                                             const float* __restrict__ Wo,
                                             const float* __restrict__ bo,
                                             float* __restrict__ out) {
    __shared__ __align__(16) float Xs[64 * 68];
    __shared__ __align__(16) float Ws[64 * 64];
    __shared__ int s_g[64];
    int t = threadIdx.x;
    int n0 = blockIdx.x * 64;
    int valid = N_NODES - n0; if (valid > 64) valid = 64;

    float4* Wsv = (float4*)Ws;
    const float4* Wg = (const float4*)Wo;
#pragma unroll
    for (int j = 0; j < 4; ++j) Wsv[t + 256 * j] = Wg[t + 256 * j];
    if (t < 64) s_g[t] = (t < valid) ? gids[n0 + t] : -1;
#pragma unroll
    for (int j = 0; j < 4; ++j) {
        int f = j * 256 + t;
        int r = f >> 4, c4 = f & 15;
        float4 x = make_float4(0.f, 0.f, 0.f, 0.f);
        if (r < valid) {
            uint2 av = *(const uint2*)&g_agg[(size_t)(n0 + r) * 64 + c4 * 4];
            const __half2* ah = (const __half2*)&av;
            float2 a0 = __half22float2(ah[0]);
            float2 a1 = __half22float2(ah[1]);
            x.x = fmaxf(a0.x, 0.f); x.y = fmaxf(a0.y, 0.f);
            x.z = fmaxf(a1.x, 0.f); x.w = fmaxf(a1.y, 0.f);
        }
        *(float4*)&Xs[r * 68 + c4 * 4] = x;
    }
    __syncthreads();

    int tx = t & 15, ty = t >> 4, r0 = ty * 4, c0 = tx * 4;
    float acc[4][4];
#pragma unroll
    for (int i = 0; i < 4; ++i)
#pragma unroll
        for (int j = 0; j < 4; ++j) acc[i][j] = 0.f;
    gemm_tile<64, 68>(Xs, Ws, r0, c0, acc);

    float4 bv = *(const float4*)&bo[c0];
    float4 y[4];
    int gg[4];
#pragma unroll
    for (int i = 0; i < 4; ++i) {
        gg[i] = s_g[r0 + i];
        y[i].x = fmaxf(acc[i][0] + bv.x, 0.f);
        y[i].y = fmaxf(acc[i][1] + bv.y, 0.f);
        y[i].z = fmaxf(acc[i][2] + bv.z, 0.f);
        y[i].w = fmaxf(acc[i][3] + bv.w, 0.f);
    }
    if (gg[0] >= 0 && gg[0] == gg[1] && gg[1] == gg[2] && gg[2] == gg[3]) {
        float4 s;
        s.x = y[0].x + y[1].x + y[2].x + y[3].x;
        s.y = y[0].y + y[1].y + y[2].y + y[3].y;
        s.z = y[0].z + y[1].z + y[2].z + y[3].z;
        s.w = y[0].w + y[1].w + y[2].w + y[3].w;
        float* base = &out[gg[0] * 64 + c0];
        atomicAdd(base + 0, s.x);
        atomicAdd(base + 1, s.y);
        atomicAdd(base + 2, s.z);
        atomicAdd(base + 3, s.w);
    } else {
#pragma unroll
        for (int i = 0; i < 4; ++i) {
            if (gg[i] >= 0) {
                float* base = &out[gg[i] * 64 + c0];
                atomicAdd(base + 0, y[i].x);
                atomicAdd(base + 1, y[i].y);
                atomicAdd(base + 2, y[i].z);
                atomicAdd(base + 3, y[i].w);
            }
        }
    }
}

// ---------------- launch ----------------------------------------------------
extern "C" void kernel_launch(void* const* d_in, const int* in_sizes, int n_in,
                              void* d_out, int out_size) {
    const float* node_feat = (const float*)d_in[0];
    const float* edge_feat = (const float*)d_in[1];
    const int*   src       = (const int*)d_in[2];
    const int*   dst       = (const int*)d_in[3];
    const int*   gids      = (const int*)d_in[5];
    int wb = n_in - 8;
    const float* Wn = (const float*)d_in[wb + 0];
    const float* bn = (const float*)d_in[wb + 1];
    const float* We = (const float*)d_in[wb + 2];
    const float* be = (const float*)d_in[wb + 3];
    const float* Wc = (const float*)d_in[wb + 4];
    const float* bc = (const float*)d_in[wb + 5];
    const float* Wo = (const float*)d_in[wb + 6];
    const float* bo = (const float*)d_in[wb + 7];
    float* out = (float*)d_out;

    // setup: node linear (+hist, weights) -> 3-phase scan -> scatter
    k_nodelin<<<(N_NODES + 63) / 64, 256>>>(node_feat, Wn, bn, dst, Wc, We);
    k_scanA<<<SCAN_NB, 1024>>>();
    k_scanB<<<1, 256>>>(out);
    k_scanC<<<SCAN_NB, 1024>>>();
    k_scatter<<<N_EDGES / 256, 256>>>(dst);

    // im init into position space (imt + curA) + tw materialization
    k_im<<<N_EDGES / 64, 256>>>(edge_feat, src, be);

    // 3 loopy-BP iterations, ping-ponging curA/curB
    k_segsum<false><<<(N_NODES * 32 + 255) / 256, 256>>>();  // reads A
    k_update<false><<<N_EDGES / 64, 256>>>(bc);              // A -> B
    k_segsum<true><<<(N_NODES * 32 + 255) / 256, 256>>>();   // reads B
    k_update<true><<<N_EDGES / 64, 256>>>(bc);               // B -> A
    k_segsum<false><<<(N_NODES * 32 + 255) / 256, 256>>>();  // reads A
    k_update<false><<<N_EDGES / 64, 256>>>(bc);              // A -> B

    // final pooling + readout + per-graph sum
    k_segsum<true><<<(N_NODES * 32 + 255) / 256, 256>>>();   // reads B
    k_out<<<(N_NODES + 63) / 64, 256>>>(gids, Wo, bo, out);
}

// round 16
// speedup vs baseline: 1.1086x; 1.1086x over previous
#include <cuda_runtime.h>
#include <cuda_fp16.h>
#include <cstdint>

#define N_NODES 50000
#define N_EDGES 800000
#define E_UND   400000
#define D 64
#define NG 128
#define SCAN_NB 49   // ceil(50000 / 1024)

// ---------------- scratch (device globals: no runtime allocation) ----------
// Messages live in CSR(dst) POSITION space: position p holds edge eidx[p].
__device__ __align__(16) __half g_node_lin[(size_t)N_NODES * D];
__device__ __align__(16) __half g_imt[(size_t)N_EDGES * D];   // imt[p] = im[rev(eidx[p])]
__device__ __align__(16) __half g_curA[(size_t)N_EDGES * D];  // ping
__device__ __align__(16) __half g_curB[(size_t)N_EDGES * D];  // pong
__device__ __align__(16) __half g_agg[(size_t)N_NODES * D];
__device__ __align__(16) __half g_Wc16[64 * 64];
__device__ __align__(16) __half g_We16[32 * 64];
__device__ int g_cnt[N_NODES];       // BSS-zero; k_scanC re-zeroes each call
__device__ int g_off[N_NODES + 1];
__device__ int g_cursor[N_NODES];
__device__ int g_part[SCAN_NB];
__device__ int g_eidx[N_EDGES];      // position -> edge
__device__ int g_pnode[N_EDGES];     // position -> node (dst of that edge)
__device__ int g_perm[N_EDGES];      // edge -> position
__device__ int g_wq[N_EDGES];        // edge e -> perm[rev(e)]
__device__ int g_tw[N_EDGES];        // position p -> perm[rev(eidx[p])]

// ---------------- mma helpers ----------------------------------------------
__device__ __forceinline__ void ldmA(uint32_t a[4], uint32_t addr) {
    asm volatile("ldmatrix.sync.aligned.m8n8.x4.shared.b16 {%0,%1,%2,%3}, [%4];"
                 : "=r"(a[0]), "=r"(a[1]), "=r"(a[2]), "=r"(a[3]) : "r"(addr));
}
__device__ __forceinline__ void ldmBt(uint32_t b[2], uint32_t addr) {
    asm volatile("ldmatrix.sync.aligned.m8n8.x2.trans.shared.b16 {%0,%1}, [%2];"
                 : "=r"(b[0]), "=r"(b[1]) : "r"(addr));
}
__device__ __forceinline__ void mma16816(float d[4], const uint32_t a[4],
                                         const uint32_t b[2]) {
    asm volatile(
        "mma.sync.aligned.m16n8k16.row.col.f32.f16.f16.f32 "
        "{%0,%1,%2,%3}, {%4,%5,%6,%7}, {%8,%9}, {%0,%1,%2,%3};"
        : "+f"(d[0]), "+f"(d[1]), "+f"(d[2]), "+f"(d[3])
        : "r"(a[0]), "r"(a[1]), "r"(a[2]), "r"(a[3]), "r"(b[0]), "r"(b[1]));
}

#define NL_THREADS 200192  // 782 blocks * 256

// ---------------- 3-phase parallel scan -------------------------------------
// A: per-block reduce of cnt -> g_part[b]
__global__ void __launch_bounds__(1024) k_scanA() {
    __shared__ int wsum[32];
    int t = threadIdx.x;
    int lane = t & 31, w = t >> 5;
    int idx = blockIdx.x * 1024 + t;
    int x = (idx < N_NODES) ? g_cnt[idx] : 0;
#pragma unroll
    for (int o = 16; o >= 1; o >>= 1) x += __shfl_down_sync(0xffffffffu, x, o);
    if (lane == 0) wsum[w] = x;
    __syncthreads();
    if (w == 0) {
        int y = wsum[lane];
#pragma unroll
        for (int o = 16; o >= 1; o >>= 1) y += __shfl_down_sync(0xffffffffu, y, o);
        if (lane == 0) g_part[blockIdx.x] = y;
    }
}

// B: serial exclusive scan of 49 partials (thread 0) + zero out
__global__ void k_scanB(float* __restrict__ out) {
    int t = threadIdx.x;
    for (int i = t; i < NG * D; i += 256) out[i] = 0.0f;
    if (t == 0) {
        int run = 0;
#pragma unroll 1
        for (int i = 0; i < SCAN_NB; ++i) {
            int v = g_part[i];
            g_part[i] = run;
            run += v;
        }
    }
}

// C: block-local exclusive scan + base; writes off/cursor, zeroes cnt
__global__ void __launch_bounds__(1024) k_scanC() {
    __shared__ int wsum[32];
    int t = threadIdx.x;
    int lane = t & 31, w = t >> 5;
    int idx = blockIdx.x * 1024 + t;
    int v = (idx < N_NODES) ? g_cnt[idx] : 0;
    int x = v;
#pragma unroll
    for (int o = 1; o < 32; o <<= 1) {
        int y = __shfl_up_sync(0xffffffffu, x, o);
        if (lane >= o) x += y;
    }
    if (lane == 31) wsum[w] = x;
    __syncthreads();
    if (w == 0) {
        int y = wsum[lane];
#pragma unroll
        for (int o = 1; o < 32; o <<= 1) {
            int z = __shfl_up_sync(0xffffffffu, y, o);
            if (lane >= o) y += z;
        }
        wsum[lane] = y;
    }
    __syncthreads();
    int excl = g_part[blockIdx.x] + x - v + (w > 0 ? wsum[w - 1] : 0);
    if (idx < N_NODES) {
        g_off[idx] = excl;
        g_cursor[idx] = excl;
        g_cnt[idx] = 0;
        if (idx == N_NODES - 1) g_off[N_NODES] = excl + v;
    }
}

// ---------------- scatter: build position-space index arrays ----------------
__global__ void k_scatter(const int* __restrict__ dst) {
    int e = blockIdx.x * blockDim.x + threadIdx.x;
    if (e < N_EDGES) {
        int d = dst[e];
        int p = atomicAdd(&g_cursor[d], 1);
        g_eidx[p] = e;
        g_pnode[p] = d;
        g_perm[e] = p;
        int r = (e < E_UND) ? e + E_UND : e - E_UND;  // rev(e)
        g_wq[r] = p;                                  // wq[rev(e)] = perm[e]
    }
}

// ---------------- segment sum: warp per node, CONTIGUOUS rows ---------------
__device__ __forceinline__ void seg_accum(uint4 v, float2& a0, float2& a1,
                                          float2& a2, float2& a3) {
    const __half2* h = (const __half2*)&v;
    float2 f0 = __half22float2(h[0]);
    float2 f1 = __half22float2(h[1]);
    float2 f2 = __half22float2(h[2]);
    float2 f3 = __half22float2(h[3]);
    a0.x += f0.x; a0.y += f0.y;
    a1.x += f1.x; a1.y += f1.y;
    a2.x += f2.x; a2.y += f2.y;
    a3.x += f3.x; a3.y += f3.y;
}

template <bool SRCB>
__global__ void __launch_bounds__(256) k_segsum() {
    int gw = (blockIdx.x * 256 + threadIdx.x) >> 5;
    int lane = threadIdx.x & 31;
    if (gw >= N_NODES) return;
    const __half* __restrict__ srcp = SRCB ? g_curB : g_curA;
    int beg = g_off[gw], end = g_off[gw + 1];
    int g = lane >> 3, s = lane & 7;
    float2 a0 = {0.f, 0.f}, a1 = {0.f, 0.f}, a2 = {0.f, 0.f}, a3 = {0.f, 0.f};
    int j = beg;
    for (; j + 16 <= end; j += 16) {
        uint4 v[4];
#pragma unroll
        for (int q = 0; q < 4; ++q)
            v[q] = *(const uint4*)(srcp + (size_t)(j + q * 4 + g) * D + s * 8);
#pragma unroll
        for (int q = 0; q < 4; ++q) seg_accum(v[q], a0, a1, a2, a3);
    }
    for (; j + 8 <= end; j += 8) {
        uint4 v[2];
#pragma unroll
        for (int q = 0; q < 2; ++q)
            v[q] = *(const uint4*)(srcp + (size_t)(j + q * 4 + g) * D + s * 8);
#pragma unroll
        for (int q = 0; q < 2; ++q) seg_accum(v[q], a0, a1, a2, a3);
    }
    for (; j < end; j += 4) {
        int r = j + g;
        uint4 v = make_uint4(0u, 0u, 0u, 0u);
        if (r < end) v = *(const uint4*)(srcp + (size_t)r * D + s * 8);
        seg_accum(v, a0, a1, a2, a3);
    }
#pragma unroll
    for (int off = 16; off >= 8; off >>= 1) {
        a0.x += __shfl_down_sync(0xffffffffu, a0.x, off);
        a0.y += __shfl_down_sync(0xffffffffu, a0.y, off);
        a1.x += __shfl_down_sync(0xffffffffu, a1.x, off);
        a1.y += __shfl_down_sync(0xffffffffu, a1.y, off);
        a2.x += __shfl_down_sync(0xffffffffu, a2.x, off);
        a2.y += __shfl_down_sync(0xffffffffu, a2.y, off);
        a3.x += __shfl_down_sync(0xffffffffu, a3.x, off);
        a3.y += __shfl_down_sync(0xffffffffu, a3.y, off);
    }
    if (lane < 8) {
        __half2 h[4];
        h[0] = __floats2half2_rn(a0.x, a0.y);
        h[1] = __floats2half2_rn(a1.x, a1.y);
        h[2] = __floats2half2_rn(a2.x, a2.y);
        h[3] = __floats2half2_rn(a3.x, a3.y);
        *(uint4*)(g_agg + (size_t)gw * D + lane * 8) = *(const uint4*)h;
    }
}

// ---------------- fp32 4x4-microtile GEMM core (small GEMMs) ---------------
template <int K, int XS>
__device__ __forceinline__ void gemm_tile(const float* __restrict__ Xs,
                                          const float* __restrict__ Ws,
                                          int r0, int c0, float acc[4][4]) {
#pragma unroll
    for (int k4 = 0; k4 < K / 4; ++k4) {
        float w[4][4];
#pragma unroll
        for (int kk = 0; kk < 4; ++kk) {
            float4 wv = *(const float4*)&Ws[(k4 * 4 + kk) * 64 + c0];
            w[kk][0] = wv.x; w[kk][1] = wv.y; w[kk][2] = wv.z; w[kk][3] = wv.w;
        }
#pragma unroll
        for (int i = 0; i < 4; ++i) {
            float4 xv = *(const float4*)&Xs[(r0 + i) * XS + k4 * 4];
#pragma unroll
            for (int jj = 0; jj < 4; ++jj) {
                acc[i][jj] = fmaf(xv.x, w[0][jj], acc[i][jj]);
                acc[i][jj] = fmaf(xv.y, w[1][jj], acc[i][jj]);
                acc[i][jj] = fmaf(xv.z, w[2][jj], acc[i][jj]);
                acc[i][jj] = fmaf(xv.w, w[3][jj], acc[i][jj]);
            }
        }
    }
}

// ---------------- A: node_lin GEMM + dst histogram + weight converts --------
__global__ void __launch_bounds__(256) k_nodelin(const float* __restrict__ nf,
                                                 const float* __restrict__ Wn,
                                                 const float* __restrict__ bn,
                                                 const int* __restrict__ dst,
                                                 const float* __restrict__ Wc,
                                                 const float* __restrict__ We) {
    __shared__ __align__(16) float Xs[64 * 68];
    __shared__ __align__(16) float Ws[64 * 64];
    int t = threadIdx.x;
    int n0 = blockIdx.x * 64;
    int valid = N_NODES - n0; if (valid > 64) valid = 64;

    {   // piggyback: dst histogram
        int gid = blockIdx.x * 256 + t;
#pragma unroll
        for (int q = 0; q < 4; ++q) {
            int e = gid + q * NL_THREADS;
            if (e < N_EDGES) atomicAdd(&g_cnt[dst[e]], 1);
        }
    }
    if (blockIdx.x == 0) {  // piggyback: fp16 weight conversion
        for (int i = t; i < 64 * 64; i += 256) g_Wc16[i] = __float2half(Wc[i]);
        for (int i = t; i < 32 * 64; i += 256) g_We16[i] = __float2half(We[i]);
    }

    float4* Wsv = (float4*)Ws;
    const float4* Wg = (const float4*)Wn;
#pragma unroll
    for (int j = 0; j < 4; ++j) Wsv[t + 256 * j] = Wg[t + 256 * j];
#pragma unroll
    for (int j = 0; j < 4; ++j) {
        int f = j * 256 + t;
        int r = f >> 4, c4 = f & 15;
        float4 x = make_float4(0.f, 0.f, 0.f, 0.f);
        if (r < valid) x = *(const float4*)&nf[(size_t)(n0 + r) * 64 + c4 * 4];
        *(float4*)&Xs[r * 68 + c4 * 4] = x;
    }
    __syncthreads();

    int tx = t & 15, ty = t >> 4, r0 = ty * 4, c0 = tx * 4;
    float acc[4][4];
#pragma unroll
    for (int i = 0; i < 4; ++i)
#pragma unroll
        for (int j = 0; j < 4; ++j) acc[i][j] = 0.f;
    gemm_tile<64, 68>(Xs, Ws, r0, c0, acc);

    float4 bv = *(const float4*)&bn[c0];
#pragma unroll
    for (int i = 0; i < 4; ++i) {
        int r = r0 + i;
        if (r < valid) {
            __half2 h[2];
            h[0] = __floats2half2_rn(acc[i][0] + bv.x, acc[i][1] + bv.y);
            h[1] = __floats2half2_rn(acc[i][2] + bv.z, acc[i][3] + bv.w);
            *(uint2*)&g_node_lin[(size_t)(n0 + r) * 64 + c0] = *(const uint2*)h;
        }
    }
}

// ---------------- B: im init via HMMA, 64 edges/block, 16x32 per warp -------
// Staged half2 epilogue (bias pre-added); writes imt[wq[f]] and curA[perm[f]].
// Preamble also materializes tw[p] = wq[eidx[p]] (consumed by k_update).
__global__ void __launch_bounds__(256) k_im(const float* __restrict__ ef,
                                            const int* __restrict__ src,
                                            const float* __restrict__ be) {
    __shared__ __align__(16) char s_buf[9728];   // Xs(5120)+Ws(4608); accH(9216)
    __shared__ int s_src[64];
    __shared__ int s_q1[64];    // perm[f]  (curA target)
    __shared__ int s_q2[64];    // wq[f]    (imt target)
    __shared__ float s_be[64];
    __half* Xs = (__half*)s_buf;                // 64*40 halves
    __half* Ws = (__half*)(s_buf + 64 * 40 * 2);// 32*72 halves
    __half* accH = (__half*)s_buf;              // 64*72 halves (phase B)
    int t = threadIdx.x;
    int e0 = blockIdx.x * 64;

    {   // piggyback: tw materialization (grid covers 3.2M threads >= N_EDGES)
        int gid = blockIdx.x * 256 + t;
        if (gid < N_EDGES) g_tw[gid] = g_wq[g_eidx[gid]];
    }
    if (t < 64) {
        s_src[t] = src[e0 + t];
        s_q1[t] = g_perm[e0 + t];
        s_q2[t] = g_wq[e0 + t];
        s_be[t] = be[t];
    }
    {   // Ws: 32x64 halves = 256 uint4, stride 72 (1 per thread)
        int row = t >> 3, col = (t & 7) * 8;
        *(uint4*)&Ws[row * 72 + col] = ((const uint4*)g_We16)[t];
    }
    {   // Xs: edge_feat fp32 -> fp16; thread = quarter row (8 cols)
        int r = t >> 2, cs = (t & 3) * 8;
        const float4* xg = (const float4*)(ef + (size_t)(e0 + r) * 32 + cs);
        float4 a = __ldcs(xg);
        float4 b = __ldcs(xg + 1);
        __half2 xh[4];
        xh[0] = __floats2half2_rn(a.x, a.y);
        xh[1] = __floats2half2_rn(a.z, a.w);
        xh[2] = __floats2half2_rn(b.x, b.y);
        xh[3] = __floats2half2_rn(b.z, b.w);
        *(uint4*)&Xs[r * 40 + cs] = *(const uint4*)xh;
    }
    __syncthreads();

    int w = t >> 5, l = t & 31;
    int rg = w >> 1, ch = w & 1;   // row group 0..3, column half 0..1
    int r0w = rg * 16;
    uint32_t baseX = (uint32_t)__cvta_generic_to_shared(Xs);
    uint32_t baseW = (uint32_t)__cvta_generic_to_shared(Ws);
    float acc[4][4];
#pragma unroll
    for (int nt = 0; nt < 4; ++nt)
#pragma unroll
        for (int q = 0; q < 4; ++q) acc[nt][q] = 0.f;

#pragma unroll
    for (int kt = 0; kt < 2; ++kt) {
        uint32_t a[4];
        uint32_t addrA = baseX + (((r0w + (l & 15)) * 40 + kt * 16 + ((l >> 4) << 3)) << 1);
        ldmA(a, addrA);
#pragma unroll
        for (int nt = 0; nt < 4; ++nt) {
            uint32_t b[2];
            uint32_t addrB = baseW + (((kt * 16 + (l & 15)) * 72 + ch * 32 + nt * 8) << 1);
            ldmBt(b, addrB);
            mma16816(acc[nt], a, b);
        }
    }
    __syncthreads();  // all MMA reads of Xs/Ws done; reuse as accH

    {   // stage (acc + bias) as half2
        int g = l >> 2, tt = l & 3;
        int row1 = r0w + g, row2 = row1 + 8;
#pragma unroll
        for (int nt = 0; nt < 4; ++nt) {
            int c = ch * 32 + nt * 8 + tt * 2;
            float bx = s_be[c], by = s_be[c + 1];
            *(__half2*)&accH[row1 * 72 + c] = __floats2half2_rn(acc[nt][0] + bx, acc[nt][1] + by);
            *(__half2*)&accH[row2 * 72 + c] = __floats2half2_rn(acc[nt][2] + bx, acc[nt][3] + by);
        }
    }
    __syncthreads();

    // writer: rows 0..63, lane owns 8 consecutive cols; scatter stores
#pragma unroll
    for (int p = 0; p < 2; ++p) {
        int row = p * 32 + (t >> 3);
        int c0 = (t & 7) * 8;
        int n = s_src[row];
        uint4 sv = *(const uint4*)&accH[row * 72 + c0];
        const __half2* sh = (const __half2*)&sv;
        uint4 nv = *(const uint4*)(g_node_lin + (size_t)n * 64 + c0);  // 8 halves
        const __half2* nh = (const __half2*)&nv;
        __half2 h[4], hr[4];
#pragma unroll
        for (int q = 0; q < 4; ++q) {
            float2 s = __half22float2(sh[q]);
            float2 nl = __half22float2(nh[q]);
            float yx = s.x + nl.x;
            float yy = s.y + nl.y;
            h[q]  = __floats2half2_rn(yx, yy);
            hr[q] = __floats2half2_rn(fmaxf(yx, 0.f), fmaxf(yy, 0.f));
        }
        *(uint4*)(g_imt + (size_t)s_q2[row] * 64 + c0) = *(const uint4*)h;
        *(uint4*)(g_curA + (size_t)s_q1[row] * 64 + c0) = *(const uint4*)hr;
    }
}

// ---------------- C: BP update, 64 positions/block, 16x32 per warp ----------
// X_p = agg[pnode[p]] - cur[p]; out = relu(X @ Wc + bc + imt[p]) -> cur'[tw[p]].
// Staged half2 epilogue with bias pre-added.
template <bool SRCB>
__global__ void __launch_bounds__(256) k_update(const float* __restrict__ bc) {
    __shared__ __align__(16) char s_buf[64 * 72 * 2 * 2];  // 18432 B
    __shared__ int s_node[64];
    __shared__ int s_tw[64];
    __shared__ float s_bc[64];
    __half* Xs = (__half*)s_buf;                 // 64*72 halves
    __half* Ws = (__half*)(s_buf + 64 * 72 * 2); // 64*72 halves
    __half* accH = (__half*)s_buf;               // 64*72 halves (phase B)
    int t = threadIdx.x;
    int p0 = blockIdx.x * 64;
    const __half* __restrict__ curs = SRCB ? g_curB : g_curA;
    __half* __restrict__ curd = SRCB ? g_curA : g_curB;

    if (t < 64) {
        s_node[t] = g_pnode[p0 + t];
        s_tw[t] = g_tw[p0 + t];
        s_bc[t] = bc[t];
    }
    // Ws: 64x64 halves = 512 uint4, stride 72
#pragma unroll
    for (int j = 0; j < 2; ++j) {
        int idx = j * 256 + t;
        int row = idx >> 3, col = (idx & 7) * 8;
        *(uint4*)&Ws[row * 72 + col] = ((const uint4*)g_Wc16)[idx];
    }
    __syncthreads();

    {   // Xs build: X = agg[node] - cur[p]; thread = quarter row (16 halves)
        int r = t >> 2, cs = (t & 3) * 16;
        int node = s_node[r];
        const uint4* ag4 = (const uint4*)(g_agg + (size_t)node * 64 + cs);
        const uint4* cu4 = (const uint4*)(curs + (size_t)(p0 + r) * 64 + cs);
        uint4 av[2] = {ag4[0], ag4[1]};
        uint4 cv[2] = {__ldcs(cu4), __ldcs(cu4 + 1)};  // old cur dead after
        const __half2* ah = (const __half2*)av;
        const __half2* ch = (const __half2*)cv;
        __half2 xh[8];
#pragma unroll
        for (int q = 0; q < 8; ++q) {
            float2 a = __half22float2(ah[q]);
            float2 c = __half22float2(ch[q]);
            xh[q] = __floats2half2_rn(a.x - c.x, a.y - c.y);
        }
        uint4* dp = (uint4*)&Xs[r * 72 + cs];
        const uint4* sp = (const uint4*)xh;
        dp[0] = sp[0]; dp[1] = sp[1];
    }
    __syncthreads();

    int w = t >> 5, l = t & 31;
    int rg = w >> 1, ch2 = w & 1;
    int r0w = rg * 16;
    uint32_t baseX = (uint32_t)__cvta_generic_to_shared(Xs);
    uint32_t baseW = (uint32_t)__cvta_generic_to_shared(Ws);
    float acc[4][4];
#pragma unroll
    for (int nt = 0; nt < 4; ++nt)
#pragma unroll
        for (int q = 0; q < 4; ++q) acc[nt][q] = 0.f;

#pragma unroll
    for (int kt = 0; kt < 4; ++kt) {
        uint32_t a[4];
        uint32_t addrA = baseX + (((r0w + (l & 15)) * 72 + kt * 16 + ((l >> 4) << 3)) << 1);
        ldmA(a, addrA);
#pragma unroll
        for (int nt = 0; nt < 4; ++nt) {
            uint32_t b[2];
            uint32_t addrB = baseW + (((kt * 16 + (l & 15)) * 72 + ch2 * 32 + nt * 8) << 1);
            ldmBt(b, addrB);
            mma16816(acc[nt], a, b);
        }
    }
    __syncthreads();  // all MMA reads of Xs/Ws done; reuse as accH

    {   // stage (acc + bias) as half2
        int g = l >> 2, tt = l & 3;
        int row1 = r0w + g, row2 = row1 + 8;
#pragma unroll
        for (int nt = 0; nt < 4; ++nt) {
            int c = ch2 * 32 + nt * 8 + tt * 2;
            float bx = s_bc[c], by = s_bc[c + 1];
            *(__half2*)&accH[row1 * 72 + c] = __floats2half2_rn(acc[nt][0] + bx, acc[nt][1] + by);
            *(__half2*)&accH[row2 * 72 + c] = __floats2half2_rn(acc[nt][2] + bx, acc[nt][3] + by);
        }
    }
    __syncthreads();

    // writer: contiguous imt read, scatter store to curd[tw[p]]
#pragma unroll
    for (int p = 0; p < 2; ++p) {
        int row = p * 32 + (t >> 3);
        int c0 = (t & 7) * 8;
        uint4 sv = *(const uint4*)&accH[row * 72 + c0];
        const __half2* sh = (const __half2*)&sv;
        uint4 imv = __ldcs((const uint4*)(g_imt + (size_t)(p0 + row) * 64 + c0));
        const __half2* mh = (const __half2*)&imv;
        __half2 h[4];
#pragma unroll
        for (int q = 0; q < 4; ++q) {
            float2 s = __half22float2(sh[q]);
            float2 m = __half22float2(mh[q]);
            h[q] = __floats2half2_rn(fmaxf(s.x + m.x, 0.f), fmaxf(s.y + m.y, 0.f));
        }
        *(uint4*)(curd + (size_t)s_tw[row] * 64 + c0) = *(const uint4*)h;
    }
}

// ---------------- D: node readout + per-graph reduction ---------------------
__global__ void __launch_bounds__(256) k_out(const int* __restrict__ gids,
                                             const float* __restrict__ Wo,
                                             const float* __restrict__ bo,
                                             float* __restrict__ out) {
    __shared__ __align__(16) float Xs[64 * 68];
    __shared__ __align__(16) float Ws[64 * 64];
    __shared__ int s_g[64];
    int t = threadIdx.x;
    int n0 = blockIdx.x * 64;
    int valid = N_NODES - n0; if (valid > 64) valid = 64;

    float4* Wsv = (float4*)Ws;
    const float4* Wg = (const float4*)Wo;
#pragma unroll
    for (int j = 0; j < 4; ++j) Wsv[t + 256 * j] = Wg[t + 256 * j];
    if (t < 64) s_g[t] = (t < valid) ? gids[n0 + t] : -1;
#pragma unroll
    for (int j = 0; j < 4; ++j) {
        int f = j * 256 + t;
        int r = f >> 4, c4 = f & 15;
        float4 x = make_float4(0.f, 0.f, 0.f, 0.f);
        if (r < valid) {
            uint2 av = *(const uint2*)&g_agg[(size_t)(n0 + r) * 64 + c4 * 4];
            const __half2* ah = (const __half2*)&av;
            float2 a0 = __half22float2(ah[0]);
            float2 a1 = __half22float2(ah[1]);
            x.x = fmaxf(a0.x, 0.f); x.y = fmaxf(a0.y, 0.f);
            x.z = fmaxf(a1.x, 0.f); x.w = fmaxf(a1.y, 0.f);
        }
        *(float4*)&Xs[r * 68 + c4 * 4] = x;
    }
    __syncthreads();

    int tx = t & 15, ty = t >> 4, r0 = ty * 4, c0 = tx * 4;
    float acc[4][4];
#pragma unroll
    for (int i = 0; i < 4; ++i)
#pragma unroll
        for (int j = 0; j < 4; ++j) acc[i][j] = 0.f;
    gemm_tile<64, 68>(Xs, Ws, r0, c0, acc);

    float4 bv = *(const float4*)&bo[c0];
    float4 y[4];
    int gg[4];
#pragma unroll
    for (int i = 0; i < 4; ++i) {
        gg[i] = s_g[r0 + i];
        y[i].x = fmaxf(acc[i][0] + bv.x, 0.f);
        y[i].y = fmaxf(acc[i][1] + bv.y, 0.f);
        y[i].z = fmaxf(acc[i][2] + bv.z, 0.f);
        y[i].w = fmaxf(acc[i][3] + bv.w, 0.f);
    }
    if (gg[0] >= 0 && gg[0] == gg[1] && gg[1] == gg[2] && gg[2] == gg[3]) {
        float4 s;
        s.x = y[0].x + y[1].x + y[2].x + y[3].x;
        s.y = y[0].y + y[1].y + y[2].y + y[3].y;
        s.z = y[0].z + y[1].z + y[2].z + y[3].z;
        s.w = y[0].w + y[1].w + y[2].w + y[3].w;
        float* base = &out[gg[0] * 64 + c0];
        atomicAdd(base + 0, s.x);
        atomicAdd(base + 1, s.y);
        atomicAdd(base + 2, s.z);
        atomicAdd(base + 3, s.w);
    } else {
#pragma unroll
        for (int i = 0; i < 4; ++i) {
            if (gg[i] >= 0) {
                float* base = &out[gg[i] * 64 + c0];
                atomicAdd(base + 0, y[i].x);
                atomicAdd(base + 1, y[i].y);
                atomicAdd(base + 2, y[i].z);
                atomicAdd(base + 3, y[i].w);
            }
        }
    }
}

// ---------------- launch ----------------------------------------------------
extern "C" void kernel_launch(void* const* d_in, const int* in_sizes, int n_in,
                              void* d_out, int out_size) {
    const float* node_feat = (const float*)d_in[0];
    const float* edge_feat = (const float*)d_in[1];
    const int*   src       = (const int*)d_in[2];
    const int*   dst       = (const int*)d_in[3];
    const int*   gids      = (const int*)d_in[5];
    int wb = n_in - 8;
    const float* Wn = (const float*)d_in[wb + 0];
    const float* bn = (const float*)d_in[wb + 1];
    const float* We = (const float*)d_in[wb + 2];
    const float* be = (const float*)d_in[wb + 3];
    const float* Wc = (const float*)d_in[wb + 4];
    const float* bc = (const float*)d_in[wb + 5];
    const float* Wo = (const float*)d_in[wb + 6];
    const float* bo = (const float*)d_in[wb + 7];
    float* out = (float*)d_out;

    // setup: node linear (+hist, weights) -> 3-phase scan -> scatter
    k_nodelin<<<(N_NODES + 63) / 64, 256>>>(node_feat, Wn, bn, dst, Wc, We);
    k_scanA<<<SCAN_NB, 1024>>>();
    k_scanB<<<1, 256>>>(out);
    k_scanC<<<SCAN_NB, 1024>>>();
    k_scatter<<<N_EDGES / 256, 256>>>(dst);

    // im init into position space (imt + curA) + tw materialization
    k_im<<<N_EDGES / 64, 256>>>(edge_feat, src, be);

    // 3 loopy-BP iterations, ping-ponging curA/curB
    k_segsum<false><<<(N_NODES * 32 + 255) / 256, 256>>>();  // reads A
    k_update<false><<<N_EDGES / 64, 256>>>(bc);              // A -> B
    k_segsum<true><<<(N_NODES * 32 + 255) / 256, 256>>>();   // reads B
    k_update<true><<<N_EDGES / 64, 256>>>(bc);               // B -> A
    k_segsum<false><<<(N_NODES * 32 + 255) / 256, 256>>>();  // reads A
    k_update<false><<<N_EDGES / 64, 256>>>(bc);              // A -> B

    // final pooling + readout + per-graph sum
    k_segsum<true><<<(N_NODES * 32 + 255) / 256, 256>>>();   // reads B
    k_out<<<(N_NODES + 63) / 64, 256>>>(gids, Wo, bo, out);
}